// round 16
// baseline (speedup 1.0000x reference)
#include <cuda.h>
#include <cuda_runtime.h>
#include <math.h>
#include <stdint.h>

#define NN 10000
#define EDGES 160000
#define DD 1280
#define MM 24
#define EEDIM 16
#define LL 6
#define PROJW 96

#if defined(__CUDA_ARCH_FEAT_SM103_ALL)
#define HAS_TCGEN05 1
#endif

__device__ __align__(16) float g_h[NN * DD];
__device__ __align__(16) float g_pos[NN * 3];
__device__ __align__(16) float g_ea[EDGES * EEDIM];   // SORTED order
__device__ __align__(16) float g_deg[NN];
__device__ __align__(16) float g_proj[(NN + 256) * PROJW];
__device__ __align__(16) float g_magg[NN * MM];
__device__ __align__(16) float g_pd[NN * 3];
__device__ __align__(16) float g_wpack[LL * DD * PROJW];
__device__ __align__(16) float g_wT[DD * DD];
__device__ int g_base[NN];     // exclusive prefix of deg
__device__ int g_cnt[NN];      // scatter counters
__device__ int g_ssrc[EDGES];  // src in sorted order
__device__ int g_sdst[EDGES];  // dst in sorted order

__device__ __forceinline__ float silu_f(float x) { return x / (1.f + __expf(-x)); }

#ifdef HAS_TCGEN05
__device__ __forceinline__ uint32_t smem_u32(const void* p) {
    uint32_t a;
    asm("{ .reg .u64 t; cvta.to.shared.u64 t, %1; cvt.u32.u64 %0, t; }" : "=r"(a) : "l"(p));
    return a;
}
__device__ __forceinline__ void mbar_wait(uint32_t addr, uint32_t parity) {
    asm volatile(
        "{\n\t.reg .pred P;\n\tWL_%=:\n\t"
        "mbarrier.try_wait.parity.shared.b64 P, [%0], %1, 0x989680;\n\t"
        "@!P bra WL_%=;\n\t}" :: "r"(addr), "r"(parity) : "memory");
}
__device__ __forceinline__ void mma_tf32(uint32_t d, uint64_t ad, uint64_t bd,
                                         uint32_t idesc, uint32_t en) {
    asm volatile(
        "{\n\t.reg .pred p;\n\tsetp.ne.u32 p, %4, 0;\n\t"
        "tcgen05.mma.cta_group::1.kind::tf32 [%0], %1, %2, %3, {%5, %5, %5, %5}, p;\n\t}"
        :: "r"(d), "l"(ad), "l"(bd), "r"(idesc), "r"(en), "r"(0u) : "memory");
}
#define DESC_BASE ((2ull << 61) | (1ull << 46) | (64ull << 32) | (1ull << 16))
#endif

// ---------------- prep: transpose + pack + zero + degree ------------------
__global__ void k_prep(const float* __restrict__ W, const float* __restrict__ mw1,
                       const float* __restrict__ nw1, const int* __restrict__ ei) {
    int idx = blockIdx.x * 256 + threadIdx.x;
    if (idx < DD * DD) {
        int k = idx / DD, n = idx % DD;
        g_wT[(size_t)n * DD + k] = W[idx];
    }
    if (idx < LL * DD * PROJW) {
        int l = idx / (DD * PROJW);
        int rem = idx % (DD * PROJW);
        int k = rem / PROJW;
        int c = rem % PROJW;
        const float* m = mw1 + (size_t)l * 2577 * 24;
        const float* n = nw1 + (size_t)l * 1304 * 24;
        float v = 0.f;
        if (c < 24) v = m[k * 24 + c];
        else if (c < 48) v = m[(1280 + k) * 24 + (c - 24)];
        else if (c < 72) v = n[k * 24 + (c - 48)];
        g_wpack[((size_t)l * PROJW + c) * DD + k] = v;
    }
    if (idx < NN * PROJW) g_proj[idx] = 0.f;
    if (idx < NN * MM) g_magg[idx] = 0.f;
    if (idx < NN * 3) g_pd[idx] = 0.f;
    if (idx < NN) {
        g_deg[idx] = 0.f;
        g_cnt[idx] = 0;
    }
    __threadfence();
    // after zeroing pass completes within this thread's scope, count degrees:
    // (separate grid-stride section; ordering is guaranteed by doing counts in
    // a second kernel-wide pass below via different index space)
    if (idx < EDGES) {
        // NOTE: g_deg[dst] may be zeroed by another block AFTER this add if
        // scheduling overlaps. To avoid the race, degree counting moved to
        // k_scatter_count below. This branch intentionally empty.
    }
}

// degree count (separate launch to avoid zero/count race)
__global__ void k_count(const int* __restrict__ ei) {
    int e = blockIdx.x * 256 + threadIdx.x;
    if (e < EDGES) atomicAdd(&g_deg[ei[EDGES + e]], 1.f);
}

// exclusive prefix sum of deg -> g_base (single block, 1024 threads)
__global__ void __launch_bounds__(1024) k_scan() {
    __shared__ int s[1024];
    __shared__ int carry;
    int tid = threadIdx.x;
    if (tid == 0) carry = 0;
    __syncthreads();
    for (int c = 0; c < (NN + 1023) / 1024; c++) {
        int i = c * 1024 + tid;
        int v = (i < NN) ? (int)g_deg[i] : 0;
        s[tid] = v;
        __syncthreads();
        for (int off = 1; off < 1024; off <<= 1) {
            int t = (tid >= off) ? s[tid - off] : 0;
            __syncthreads();
            s[tid] += t;
            __syncthreads();
        }
        if (i < NN) g_base[i] = carry + s[tid] - v;
        __syncthreads();
        if (tid == 1023) carry += s[1023];
        __syncthreads();
    }
}

// scatter edges into dst-sorted order; emit sorted src/dst + edge attrs
__global__ void k_scatter(const int* __restrict__ ei, const float* __restrict__ pos0) {
    int e = blockIdx.x * 256 + threadIdx.x;
    if (e >= EDGES) return;
    int src = ei[e];
    int dst = ei[EDGES + e];
    int p = g_base[dst] + atomicAdd(&g_cnt[dst], 1);
    g_ssrc[p] = src;
    g_sdst[p] = dst;
    float dx = pos0[src * 3 + 0] - pos0[dst * 3 + 0];
    float dy = pos0[src * 3 + 1] - pos0[dst * 3 + 1];
    float dz = pos0[src * 3 + 2] - pos0[dst * 3 + 2];
    float dist = sqrtf(dx * dx + dy * dy + dz * dz);
#pragma unroll
    for (int t = 0; t < 8; t++) {
        float fr = expf(-1.1512925464970229f * (float)t);
        float a = dist * fr;
        float sn, cs;
        sincosf(a, &sn, &cs);
        g_ea[p * 16 + 2 * t] = sn;
        g_ea[p * 16 + 2 * t + 1] = cs;
    }
}

// ---------------- TMA-fed tcgen05 tf32 GEMM -------------------------------
template <int BN, int MT, bool EMB, int NSTG, int LAG>
__global__ void __launch_bounds__(128) k_mma(const __grid_constant__ CUtensorMap tmA,
                                             const __grid_constant__ CUtensorMap tmB,
                                             const float* __restrict__ bias,
                                             float* __restrict__ C, int ldc, int zc,
                                             int CSP, int CTOT) {
#ifdef HAS_TCGEN05
    constexpr int ACH = 128 * 128;
    constexpr int BCH = BN * 128;
    constexpr int STG = MT * ACH + BCH;
    constexpr uint32_t TCOLS = (MT * BN > 256) ? 512u : 256u;
    constexpr uint32_t IDESC =
        (1u << 4) | (2u << 7) | (2u << 10) | ((uint32_t)(BN / 8) << 17) | (8u << 24);
    extern __shared__ char smem[];
    uint32_t sb = smem_u32(smem);
    int tid = threadIdx.x;
    int wid = tid >> 5, lane = tid & 31;
    int bn = EMB ? blockIdx.x * BN : 0;
    int bm = blockIdx.y * (MT * 128);
    int cbeg = EMB ? 0 : blockIdx.x * CSP;
    int cend = EMB ? CTOT : min(cbeg + CSP, CTOT);
    const uint32_t FULL0 = sb + 8;
    const uint32_t DONE0 = sb + 96;

    if (wid == 0) {
        asm volatile("tcgen05.alloc.cta_group::1.sync.aligned.shared::cta.b32 [%0], %1;"
                     :: "r"(sb), "r"(TCOLS) : "memory");
    }
    if (tid == 0) {
#pragma unroll
        for (int b = 0; b < NSTG; b++)
            asm volatile("mbarrier.init.shared.b64 [%0], %1;"
                         :: "r"(FULL0 + 8 * b), "r"(1u) : "memory");
#pragma unroll
        for (int b = 0; b < 4; b++)
            asm volatile("mbarrier.init.shared.b64 [%0], %1;"
                         :: "r"(DONE0 + 8 * b), "r"(1u) : "memory");
    }
    __syncthreads();
    uint32_t tmem;
    asm volatile("ld.shared.b32 %0, [%1];" : "=r"(tmem) : "r"(sb));

    const int NIT = cend - cbeg;

    if (tid == 0) {
        auto load_tile = [&](int li) {
            int stg = li % NSTG;
            uint32_t base = sb + 1024 + (uint32_t)stg * STG;
            uint32_t mb = FULL0 + 8 * stg;
            int kco = (cbeg + li) * 32;
            asm volatile("mbarrier.arrive.expect_tx.shared.b64 _, [%0], %1;"
                         :: "r"(mb), "r"((uint32_t)STG) : "memory");
#pragma unroll
            for (int mt = 0; mt < MT; mt++)
                asm volatile(
                    "cp.async.bulk.tensor.3d.shared::cta.global.tile.mbarrier::complete_tx::bytes "
                    "[%0], [%1, {%2, %3, %4}], [%5];"
                    :: "r"(base + mt * ACH), "l"(&tmA),
                       "r"(kco), "r"(bm + mt * 128), "r"(0), "r"(mb) : "memory");
            asm volatile(
                "cp.async.bulk.tensor.3d.shared::cta.global.tile.mbarrier::complete_tx::bytes "
                "[%0], [%1, {%2, %3, %4}], [%5];"
                :: "r"(base + MT * ACH), "l"(&tmB),
                   "r"(kco), "r"(bn), "r"(zc), "r"(mb) : "memory");
        };
#pragma unroll
        for (int p = 0; p < NSTG; p++)
            if (p < NIT) load_tile(p);

        for (int li = 0; li < NIT; li++) {
            int stg = li % NSTG;
            mbar_wait(FULL0 + 8 * stg, (uint32_t)((li / NSTG) & 1));
            uint32_t base = sb + 1024 + (uint32_t)stg * STG;
            uint64_t bd = DESC_BASE | ((uint64_t)((base + MT * ACH) >> 4) & 0x3FFF);
#pragma unroll
            for (int mt = 0; mt < MT; mt++) {
                uint64_t ad = DESC_BASE | ((uint64_t)((base + mt * ACH) >> 4) & 0x3FFF);
#pragma unroll
                for (int k = 0; k < 4; k++)
                    mma_tf32(tmem + mt * BN, ad + k * 2, bd + k * 2, IDESC,
                             (uint32_t)((li | k) != 0));
            }
            asm volatile(
                "tcgen05.commit.cta_group::1.mbarrier::arrive::one.shared::cluster.b64 [%0];"
                :: "r"(DONE0 + 8 * (li & 3)) : "memory");
            if (li >= LAG) {
                int j = li - LAG;
                mbar_wait(DONE0 + 8 * (j & 3), (uint32_t)((j >> 2) & 1));
                if (j + NSTG < NIT) load_tile(j + NSTG);
            }
        }
        for (int j = (NIT - LAG > 0 ? NIT - LAG : 0); j < NIT; j++)
            mbar_wait(DONE0 + 8 * (j & 3), (uint32_t)((j >> 2) & 1));
    }
    __syncthreads();

    constexpr int RS = BN + 4;
    float* sc = (float*)(smem + 1024);
    asm volatile("tcgen05.fence::after_thread_sync;" ::: "memory");
#pragma unroll
    for (int mt = 0; mt < MT; mt++) {
        if (wid < 4) {
            int rloc = wid * 32 + lane;
#pragma unroll
            for (int cb = 0; cb < BN; cb += 32) {
                uint32_t d[32];
                asm volatile(
                    "tcgen05.ld.sync.aligned.32x32b.x32.b32 "
                    "{%0, %1, %2, %3, %4, %5, %6, %7, "
                    " %8, %9, %10, %11, %12, %13, %14, %15, "
                    " %16, %17, %18, %19, %20, %21, %22, %23, "
                    " %24, %25, %26, %27, %28, %29, %30, %31}, [%32];"
                    : "=r"(d[0]), "=r"(d[1]), "=r"(d[2]), "=r"(d[3]),
                      "=r"(d[4]), "=r"(d[5]), "=r"(d[6]), "=r"(d[7]),
                      "=r"(d[8]), "=r"(d[9]), "=r"(d[10]), "=r"(d[11]),
                      "=r"(d[12]), "=r"(d[13]), "=r"(d[14]), "=r"(d[15]),
                      "=r"(d[16]), "=r"(d[17]), "=r"(d[18]), "=r"(d[19]),
                      "=r"(d[20]), "=r"(d[21]), "=r"(d[22]), "=r"(d[23]),
                      "=r"(d[24]), "=r"(d[25]), "=r"(d[26]), "=r"(d[27]),
                      "=r"(d[28]), "=r"(d[29]), "=r"(d[30]), "=r"(d[31])
                    : "r"(tmem + mt * BN + cb));
                asm volatile("tcgen05.wait::ld.sync.aligned;" ::: "memory");
                float* row = sc + rloc * RS + cb;
#pragma unroll
                for (int c = 0; c < 32; c += 4)
                    *(float4*)(row + c) = make_float4(__uint_as_float(d[c]),
                                                      __uint_as_float(d[c + 1]),
                                                      __uint_as_float(d[c + 2]),
                                                      __uint_as_float(d[c + 3]));
            }
            asm volatile("tcgen05.fence::before_thread_sync;" ::: "memory");
        }
        __syncthreads();
        int rb = bm + mt * 128;
        for (int idx = tid; idx < 128 * (BN / 4); idx += 128) {
            int r = idx / (BN / 4), q = idx % (BN / 4);
            if (rb + r < NN) {
                float4 v = *(float4*)(sc + r * RS + q * 4);
                if (EMB) {
                    float4 bv = *(const float4*)(bias + bn + q * 4);
                    v.x += bv.x; v.y += bv.y; v.z += bv.z; v.w += bv.w;
                    *(float4*)(C + (size_t)(rb + r) * ldc + bn + q * 4) = v;
                } else {
                    atomicAdd((float4*)(C + (size_t)(rb + r) * ldc + bn + q * 4), v);
                }
            }
        }
        __syncthreads();
    }
    if (wid == 0) {
        asm volatile("tcgen05.relinquish_alloc_permit.cta_group::1.sync.aligned;");
        asm volatile("tcgen05.dealloc.cta_group::1.sync.aligned.b32 %0, %1;"
                     :: "r"(tmem), "r"(TCOLS));
    }
#else
    (void)tmA; (void)tmB; (void)bias; (void)C; (void)ldc; (void)zc; (void)CSP; (void)CTOT;
#endif
}

// ---------------- per-edge message MLP + scatter (dst-sorted order) -------
template <bool COORD>
__global__ void __launch_bounds__(256) k_edge(const float* __restrict__ mw1l,
                                              const float* __restrict__ mb1l,
                                              const float* __restrict__ mw2l,
                                              const float* __restrict__ mb2l,
                                              const float* __restrict__ cw1l,
                                              const float* __restrict__ cb1l,
                                              const float* __restrict__ cw2l) {
    __shared__ float sEA[16 * 24];
    __shared__ float sWr[24], sB1[24], sB2[24];
    __shared__ float sW2[24 * 24];
    __shared__ float sC1[24 * 24], sCB[24], sC2[24];
    int tid = threadIdx.x;
    for (int i = tid; i < 16 * 24; i += 256) sEA[i] = mw1l[2560 * 24 + i];
    for (int i = tid; i < 576; i += 256) sW2[i] = mw2l[i];
    if (tid < 24) {
        sWr[tid] = mw1l[2576 * 24 + tid];
        sB1[tid] = mb1l[tid];
        sB2[tid] = mb2l[tid];
    }
    if (COORD) {
        for (int i = tid; i < 576; i += 256) sC1[i] = cw1l[i];
        if (tid < 24) {
            sCB[tid] = cb1l[tid];
            sC2[tid] = cw2l[tid];
        }
    }
    __syncthreads();
    int e = blockIdx.x * 256 + tid;   // SORTED index
    if (e >= EDGES) return;
    int src = g_ssrc[e], dst = g_sdst[e];
    float px = g_pos[src * 3 + 0] - g_pos[dst * 3 + 0];
    float py = g_pos[src * 3 + 1] - g_pos[dst * 3 + 1];
    float pz = g_pos[src * 3 + 2] - g_pos[dst * 3 + 2];
    float radial = px * px + py * py + pz * pz;

    float eav[16];
    {
        const float4* ea4 = (const float4*)(g_ea + (size_t)e * 16);
#pragma unroll
        for (int q = 0; q < 4; q++) {
            float4 v = ea4[q];
            eav[4 * q + 0] = v.x;
            eav[4 * q + 1] = v.y;
            eav[4 * q + 2] = v.z;
            eav[4 * q + 3] = v.w;
        }
    }

    float m1[24];
    const float4* pa = (const float4*)(g_proj + (size_t)dst * PROJW);
    const float4* pb = (const float4*)(g_proj + (size_t)src * PROJW + 24);
#pragma unroll
    for (int q = 0; q < 6; q++) {
        float4 a = pa[q], b = pb[q];
        m1[4 * q + 0] = a.x + b.x;
        m1[4 * q + 1] = a.y + b.y;
        m1[4 * q + 2] = a.z + b.z;
        m1[4 * q + 3] = a.w + b.w;
    }
#pragma unroll
    for (int k = 0; k < 24; k++) m1[k] += sB1[k] + radial * sWr[k];
#pragma unroll 4
    for (int f = 0; f < 16; f++) {
        float av = eav[f];
#pragma unroll
        for (int k = 0; k < 24; k++) m1[k] += av * sEA[f * 24 + k];
    }
#pragma unroll
    for (int k = 0; k < 24; k++) m1[k] = silu_f(m1[k]);

    float m2[24];
#pragma unroll
    for (int k = 0; k < 24; k++) m2[k] = sB2[k];
#pragma unroll 4
    for (int j = 0; j < 24; j++) {
        float mv = m1[j];
#pragma unroll
        for (int k = 0; k < 24; k++) m2[k] += mv * sW2[j * 24 + k];
    }
#pragma unroll
    for (int k = 0; k < 24; k++) m2[k] = silu_f(m2[k]);

    float* agg = g_magg + (size_t)dst * 24;
#if __CUDA_ARCH__ >= 900
#pragma unroll
    for (int q = 0; q < 6; q++)
        atomicAdd((float4*)(agg + q * 4),
                  make_float4(m2[q * 4], m2[q * 4 + 1], m2[q * 4 + 2], m2[q * 4 + 3]));
#else
#pragma unroll
    for (int k = 0; k < 24; k++) atomicAdd(agg + k, m2[k]);
#endif

    if (COORD) {
        float w = 0.f;
#pragma unroll 4
        for (int k = 0; k < 24; k++) {
            float t = sCB[k];
#pragma unroll
            for (int j = 0; j < 24; j++) t += m2[j] * sC1[j * 24 + k];
            w += silu_f(t) * sC2[k];
        }
        atomicAdd(&g_pd[dst * 3 + 0], px * w);
        atomicAdd(&g_pd[dst * 3 + 1], py * w);
        atomicAdd(&g_pd[dst * 3 + 2], pz * w);
    }
}

// ---------------- per-node: node MLP + residual + LayerNorm + pos ---------
__global__ void __launch_bounds__(320) k_node(const float* __restrict__ nw1l,
                                              const float* __restrict__ nb1l,
                                              const float* __restrict__ nw2l,
                                              const float* __restrict__ nb2l,
                                              const float* __restrict__ lngl,
                                              const float* __restrict__ lnbl) {
    __shared__ float sW1m[576];
    __shared__ float sNB1[24];
    __shared__ float sT[4 * 24];
    __shared__ float sRed[10 * 8];
    __shared__ float sMu[4], sRs[4];

    int tid = threadIdx.x;
    int lane = tid & 31, wid = tid >> 5;
    int d0 = tid * 4;

    float4 w2[24];
#pragma unroll
    for (int m = 0; m < 24; m++) w2[m] = *(const float4*)(nw2l + m * DD + d0);
    float4 b2 = *(const float4*)(nb2l + d0);
    float4 gg = *(const float4*)(lngl + d0);
    float4 bb = *(const float4*)(lnbl + d0);

    for (int i = tid; i < 576; i += 320) sW1m[i] = nw1l[1280 * 24 + i];
    if (tid < 24) sNB1[tid] = nb1l[tid];
    __syncthreads();

    for (int i0 = blockIdx.x * 4; i0 < NN; i0 += gridDim.x * 4) {
        float4 hv[4];
#pragma unroll
        for (int b = 0; b < 4; b++) {
            int node = i0 + b;
            if (node < NN) hv[b] = *(const float4*)(g_h + (size_t)node * DD + d0);
        }

        if (wid < 4) {
            int node = i0 + wid;
            if (node < NN) {
                int lk = (lane < 24) ? lane : 0;
                float inv = 1.f / fmaxf(g_deg[node], 1.f);
                float ms = g_magg[(size_t)node * 24 + lk] * inv;
                float t = sNB1[lk] + g_proj[(size_t)node * PROJW + 48 + lk];
#pragma unroll
                for (int k = 0; k < 24; k++) {
                    float msk = __shfl_sync(0xffffffff, ms, k);
                    t += msk * sW1m[k * 24 + lk];
                }
                __syncwarp();
                if (lane < 24) {
                    sT[wid * 24 + lane] = silu_f(t);
                    g_magg[(size_t)node * 24 + lane] = 0.f;
                    *(float4*)(g_proj + (size_t)node * PROJW + lane * 4) =
                        make_float4(0.f, 0.f, 0.f, 0.f);
                }
            }
        } else if (wid == 4 && lane < 12) {
            int node = i0 + lane / 3, c = lane % 3;
            if (node < NN) {
                g_pos[node * 3 + c] += g_pd[node * 3 + c];
                g_pd[node * 3 + c] = 0.f;
            }
        }
        __syncthreads();

        float4 hn[4];
        float s[4], ss[4];
#pragma unroll
        for (int b = 0; b < 4; b++) {
            int node = i0 + b;
            s[b] = 0.f; ss[b] = 0.f;
            if (node < NN) {
                float4 acc = b2;
#pragma unroll
                for (int m = 0; m < 24; m++) {
                    float t = sT[b * 24 + m];
                    acc.x += t * w2[m].x;
                    acc.y += t * w2[m].y;
                    acc.z += t * w2[m].z;
                    acc.w += t * w2[m].w;
                }
                hn[b].x = hv[b].x + acc.x;
                hn[b].y = hv[b].y + acc.y;
                hn[b].z = hv[b].z + acc.z;
                hn[b].w = hv[b].w + acc.w;
                s[b] = hn[b].x + hn[b].y + hn[b].z + hn[b].w;
                ss[b] = hn[b].x * hn[b].x + hn[b].y * hn[b].y +
                        hn[b].z * hn[b].z + hn[b].w * hn[b].w;
            }
        }
#pragma unroll
        for (int off = 16; off > 0; off >>= 1) {
#pragma unroll
            for (int b = 0; b < 4; b++) {
                s[b] += __shfl_down_sync(0xffffffff, s[b], off);
                ss[b] += __shfl_down_sync(0xffffffff, ss[b], off);
            }
        }
        if (lane == 0) {
#pragma unroll
            for (int b = 0; b < 4; b++) {
                sRed[wid * 8 + b * 2] = s[b];
                sRed[wid * 8 + b * 2 + 1] = ss[b];
            }
        }
        __syncthreads();
        if (tid < 4) {
            float S = 0.f, SS = 0.f;
#pragma unroll
            for (int w = 0; w < 10; w++) {
                S += sRed[w * 8 + tid * 2];
                SS += sRed[w * 8 + tid * 2 + 1];
            }
            float mu = S * (1.f / 1280.f);
            float var = SS * (1.f / 1280.f) - mu * mu;
            sMu[tid] = mu;
            sRs[tid] = rsqrtf(var + 1e-5f);
        }
        __syncthreads();
#pragma unroll
        for (int b = 0; b < 4; b++) {
            int node = i0 + b;
            if (node < NN) {
                float mu = sMu[b], rs = sRs[b];
                float4 o;
                o.x = (hn[b].x - mu) * rs * gg.x + bb.x;
                o.y = (hn[b].y - mu) * rs * gg.y + bb.y;
                o.z = (hn[b].z - mu) * rs * gg.z + bb.z;
                o.w = (hn[b].w - mu) * rs * gg.w + bb.w;
                *(float4*)(g_h + (size_t)node * DD + d0) = o;
            }
        }
        __syncthreads();
    }
}

typedef CUresult (*tmap_fn_t)(CUtensorMap*, CUtensorMapDataType, cuuint32_t, void*,
                              const cuuint64_t*, const cuuint64_t*, const cuuint32_t*,
                              const cuuint32_t*, CUtensorMapInterleave, CUtensorMapSwizzle,
                              CUtensorMapL2promotion, CUtensorMapFloatOOBfill);

static tmap_fn_t get_tmap_fn() {
    static tmap_fn_t fn = nullptr;
    if (!fn) {
        void* p = nullptr;
        cudaDriverEntryPointQueryResult st;
        cudaGetDriverEntryPoint("cuTensorMapEncodeTiled", &p, cudaEnableDefault, &st);
        fn = (tmap_fn_t)p;
    }
    return fn;
}

static void make_tmap(CUtensorMap* tm, void* base, uint64_t d0, uint64_t d1, uint64_t d2,
                      uint64_t s1, uint64_t s2, uint32_t b0, uint32_t b1) {
    cuuint64_t dims[3] = {d0, d1, d2};
    cuuint64_t strides[2] = {s1, s2};
    cuuint32_t box[3] = {b0, b1, 1};
    cuuint32_t es[3] = {1, 1, 1};
    get_tmap_fn()(tm, CU_TENSOR_MAP_DATA_TYPE_FLOAT32, 3, base, dims, strides, box, es,
                  CU_TENSOR_MAP_INTERLEAVE_NONE, CU_TENSOR_MAP_SWIZZLE_128B,
                  CU_TENSOR_MAP_L2_PROMOTION_L2_128B, CU_TENSOR_MAP_FLOAT_OOB_FILL_NONE);
}

extern "C" void kernel_launch(void* const* d_in, const int* in_sizes, int n_in,
                              void* d_out, int out_size) {
    const float* h0 = (const float*)d_in[0];
    const float* pos0 = (const float*)d_in[1];
    const int* ei = (const int*)d_in[2];
    const float* embW = (const float*)d_in[3];
    const float* embB = (const float*)d_in[4];
    const float* mw1 = (const float*)d_in[5];
    const float* mb1 = (const float*)d_in[6];
    const float* mw2 = (const float*)d_in[7];
    const float* mb2 = (const float*)d_in[8];
    const float* cw1 = (const float*)d_in[9];
    const float* cb1 = (const float*)d_in[10];
    const float* cw2 = (const float*)d_in[11];
    const float* nw1 = (const float*)d_in[12];
    const float* nb1 = (const float*)d_in[13];
    const float* nw2 = (const float*)d_in[14];
    const float* nb2 = (const float*)d_in[15];
    const float* lng = (const float*)d_in[16];
    const float* lnb = (const float*)d_in[17];
    float* out = (float*)d_out;

    const int SMEM_EMB = 1024 + 3 * (2 * 128 * 128 + 256 * 128);
    const int SMEM_PROJ = 1024 + 4 * (2 * 128 * 128 + PROJW * 128);

    cudaFuncSetAttribute(k_mma<256, 2, true, 3, 1>,
                         cudaFuncAttributeMaxDynamicSharedMemorySize, SMEM_EMB);
    cudaFuncSetAttribute(k_mma<PROJW, 2, false, 4, 2>,
                         cudaFuncAttributeMaxDynamicSharedMemorySize, SMEM_PROJ);

    void* p_pos = nullptr;
    void* p_h = nullptr;
    void* p_proj = nullptr;
    void* p_wT = nullptr;
    void* p_wpack = nullptr;
    cudaGetSymbolAddress(&p_pos, g_pos);
    cudaGetSymbolAddress(&p_h, g_h);
    cudaGetSymbolAddress(&p_proj, g_proj);
    cudaGetSymbolAddress(&p_wT, g_wT);
    cudaGetSymbolAddress(&p_wpack, g_wpack);

    CUtensorMap tmA_emb, tmB_emb, tmA_proj, tmB_proj;
    make_tmap(&tmA_emb, (void*)h0, DD, NN, 1, (uint64_t)DD * 4, (uint64_t)DD * NN * 4, 32, 128);
    make_tmap(&tmB_emb, p_wT, DD, DD, 1, (uint64_t)DD * 4, (uint64_t)DD * DD * 4, 32, 256);
    make_tmap(&tmA_proj, p_h, DD, NN, 1, (uint64_t)DD * 4, (uint64_t)DD * NN * 4, 32, 128);
    make_tmap(&tmB_proj, p_wpack, DD, PROJW, LL, (uint64_t)DD * 4,
              (uint64_t)DD * PROJW * 4, 32, PROJW);

    cudaMemcpyAsync(p_pos, pos0, NN * 3 * sizeof(float), cudaMemcpyDeviceToDevice, 0);
    k_prep<<<(DD * DD + 255) / 256, 256>>>(embW, mw1, nw1, ei);
    k_count<<<(EDGES + 255) / 256, 256>>>(ei);
    k_scan<<<1, 1024>>>();
    k_scatter<<<(EDGES + 255) / 256, 256>>>(ei, pos0);

    // emb: MT=2, BN=256, grid (5 N-tiles, 40 M-tiles)
    k_mma<256, 2, true, 3, 1><<<dim3(5, 40), 128, SMEM_EMB>>>(
        tmA_emb, tmB_emb, embB, (float*)p_h, DD, 0, 0, DD / 32);

    for (int l = 0; l < LL; l++) {
        k_mma<PROJW, 2, false, 4, 2><<<dim3(3, 40), 128, SMEM_PROJ>>>(
            tmA_proj, tmB_proj, nullptr, (float*)p_proj, PROJW, l, 14, DD / 32);

        const float* mw1l = mw1 + (size_t)l * 2577 * 24;
        if (l < LL - 1) {
            k_edge<true><<<(EDGES + 255) / 256, 256>>>(
                mw1l, mb1 + l * 24, mw2 + l * 576, mb2 + l * 24,
                cw1 + l * 576, cb1 + l * 24, cw2 + l * 24);
        } else {
            k_edge<false><<<(EDGES + 255) / 256, 256>>>(
                mw1l, mb1 + l * 24, mw2 + l * 576, mb2 + l * 24,
                nullptr, nullptr, nullptr);
        }
        k_node<<<148, 320>>>(
            nw1 + (size_t)l * 1304 * 24, nb1 + l * 24,
            nw2 + (size_t)l * 24 * 1280, nb2 + l * 1280,
            lng + l * 1280, lnb + l * 1280);
    }

    cudaMemcpyAsync(out, p_h, (size_t)NN * DD * sizeof(float), cudaMemcpyDeviceToDevice, 0);
    cudaMemcpyAsync(out + (size_t)NN * DD, p_pos, NN * 3 * sizeof(float), cudaMemcpyDeviceToDevice, 0);
}

// round 17
// speedup vs baseline: 1.0627x; 1.0627x over previous
#include <cuda.h>
#include <cuda_runtime.h>
#include <math.h>
#include <stdint.h>

#define NN 10000
#define EDGES 160000
#define DD 1280
#define MM 24
#define EEDIM 16
#define LL 6
#define PROJW 96

#if defined(__CUDA_ARCH_FEAT_SM103_ALL)
#define HAS_TCGEN05 1
#endif

__device__ __align__(16) float g_h[NN * DD];
__device__ __align__(16) float g_pos[NN * 3];
__device__ __align__(16) float g_ea[EDGES * EEDIM];
__device__ __align__(16) float g_deg[NN];
__device__ __align__(16) float g_proj[(NN + 256) * PROJW];
__device__ __align__(16) float g_magg[NN * MM];
__device__ __align__(16) float g_pd[NN * 3];
__device__ __align__(16) float g_wpack[LL * DD * PROJW];
__device__ __align__(16) float g_wT[DD * DD];

__device__ __forceinline__ float silu_f(float x) { return x / (1.f + __expf(-x)); }

#ifdef HAS_TCGEN05
__device__ __forceinline__ uint32_t smem_u32(const void* p) {
    uint32_t a;
    asm("{ .reg .u64 t; cvta.to.shared.u64 t, %1; cvt.u32.u64 %0, t; }" : "=r"(a) : "l"(p));
    return a;
}
__device__ __forceinline__ void mbar_wait(uint32_t addr, uint32_t parity) {
    asm volatile(
        "{\n\t.reg .pred P;\n\tWL_%=:\n\t"
        "mbarrier.try_wait.parity.shared.b64 P, [%0], %1, 0x989680;\n\t"
        "@!P bra WL_%=;\n\t}" :: "r"(addr), "r"(parity) : "memory");
}
__device__ __forceinline__ void mma_tf32(uint32_t d, uint64_t ad, uint64_t bd,
                                         uint32_t idesc, uint32_t en) {
    asm volatile(
        "{\n\t.reg .pred p;\n\tsetp.ne.u32 p, %4, 0;\n\t"
        "tcgen05.mma.cta_group::1.kind::tf32 [%0], %1, %2, %3, {%5, %5, %5, %5}, p;\n\t}"
        :: "r"(d), "l"(ad), "l"(bd), "r"(idesc), "r"(en), "r"(0u) : "memory");
}
#define DESC_BASE ((2ull << 61) | (1ull << 46) | (64ull << 32) | (1ull << 16))
#endif

// ---------------- prep: transpose + pack + edge attrs + degree ------------
// (g_deg / g_magg / g_pd / g_proj are pre-zeroed via cudaMemsetAsync)
__global__ void k_prep(const float* __restrict__ W, const float* __restrict__ mw1,
                       const float* __restrict__ nw1, const int* __restrict__ ei,
                       const float* __restrict__ pos0) {
    int idx = blockIdx.x * 256 + threadIdx.x;
    if (idx < DD * DD) {
        int k = idx / DD, n = idx % DD;
        g_wT[(size_t)n * DD + k] = W[idx];
    }
    if (idx < LL * DD * PROJW) {
        int l = idx / (DD * PROJW);
        int rem = idx % (DD * PROJW);
        int k = rem / PROJW;
        int c = rem % PROJW;
        const float* m = mw1 + (size_t)l * 2577 * 24;
        const float* n = nw1 + (size_t)l * 1304 * 24;
        float v = 0.f;
        if (c < 24) v = m[k * 24 + c];
        else if (c < 48) v = m[(1280 + k) * 24 + (c - 24)];
        else if (c < 72) v = n[k * 24 + (c - 48)];
        g_wpack[((size_t)l * PROJW + c) * DD + k] = v;
    }
    if (idx < EDGES) {
        int src = ei[idx];
        int dst = ei[EDGES + idx];
        float dx = pos0[src * 3 + 0] - pos0[dst * 3 + 0];
        float dy = pos0[src * 3 + 1] - pos0[dst * 3 + 1];
        float dz = pos0[src * 3 + 2] - pos0[dst * 3 + 2];
        float dist = sqrtf(dx * dx + dy * dy + dz * dz);
#pragma unroll
        for (int t = 0; t < 8; t++) {
            float fr = expf(-1.1512925464970229f * (float)t);
            float a = dist * fr;
            float sn, cs;
            sincosf(a, &sn, &cs);
            g_ea[idx * 16 + 2 * t] = sn;
            g_ea[idx * 16 + 2 * t + 1] = cs;
        }
        atomicAdd(&g_deg[dst], 1.f);
    }
}

// ---------------- TMA-fed tcgen05 tf32 GEMM -------------------------------
template <int BN, int MT, bool EMB, int NSTG, int LAG>
__global__ void __launch_bounds__(128) k_mma(const __grid_constant__ CUtensorMap tmA,
                                             const __grid_constant__ CUtensorMap tmB,
                                             const float* __restrict__ bias,
                                             float* __restrict__ C, int ldc, int zc,
                                             int CSP, int CTOT) {
#ifdef HAS_TCGEN05
    constexpr int ACH = 128 * 128;
    constexpr int BCH = BN * 128;
    constexpr int STG = MT * ACH + BCH;
    constexpr uint32_t TCOLS = (MT * BN > 256) ? 512u : 256u;
    constexpr uint32_t IDESC =
        (1u << 4) | (2u << 7) | (2u << 10) | ((uint32_t)(BN / 8) << 17) | (8u << 24);
    extern __shared__ char smem[];
    uint32_t sb = smem_u32(smem);
    int tid = threadIdx.x;
    int wid = tid >> 5, lane = tid & 31;
    int bn = EMB ? blockIdx.x * BN : 0;
    int bm = blockIdx.y * (MT * 128);
    int cbeg = EMB ? 0 : blockIdx.x * CSP;
    int cend = EMB ? CTOT : min(cbeg + CSP, CTOT);
    const uint32_t FULL0 = sb + 8;
    const uint32_t DONE0 = sb + 96;

    if (wid == 0) {
        asm volatile("tcgen05.alloc.cta_group::1.sync.aligned.shared::cta.b32 [%0], %1;"
                     :: "r"(sb), "r"(TCOLS) : "memory");
    }
    if (tid == 0) {
#pragma unroll
        for (int b = 0; b < NSTG; b++)
            asm volatile("mbarrier.init.shared.b64 [%0], %1;"
                         :: "r"(FULL0 + 8 * b), "r"(1u) : "memory");
#pragma unroll
        for (int b = 0; b < 4; b++)
            asm volatile("mbarrier.init.shared.b64 [%0], %1;"
                         :: "r"(DONE0 + 8 * b), "r"(1u) : "memory");
    }
    __syncthreads();
    uint32_t tmem;
    asm volatile("ld.shared.b32 %0, [%1];" : "=r"(tmem) : "r"(sb));

    const int NIT = cend - cbeg;

    if (tid == 0) {
        auto load_tile = [&](int li) {
            int stg = li % NSTG;
            uint32_t base = sb + 1024 + (uint32_t)stg * STG;
            uint32_t mb = FULL0 + 8 * stg;
            int kco = (cbeg + li) * 32;
            asm volatile("mbarrier.arrive.expect_tx.shared.b64 _, [%0], %1;"
                         :: "r"(mb), "r"((uint32_t)STG) : "memory");
#pragma unroll
            for (int mt = 0; mt < MT; mt++)
                asm volatile(
                    "cp.async.bulk.tensor.3d.shared::cta.global.tile.mbarrier::complete_tx::bytes "
                    "[%0], [%1, {%2, %3, %4}], [%5];"
                    :: "r"(base + mt * ACH), "l"(&tmA),
                       "r"(kco), "r"(bm + mt * 128), "r"(0), "r"(mb) : "memory");
            asm volatile(
                "cp.async.bulk.tensor.3d.shared::cta.global.tile.mbarrier::complete_tx::bytes "
                "[%0], [%1, {%2, %3, %4}], [%5];"
                :: "r"(base + MT * ACH), "l"(&tmB),
                   "r"(kco), "r"(bn), "r"(zc), "r"(mb) : "memory");
        };
#pragma unroll
        for (int p = 0; p < NSTG; p++)
            if (p < NIT) load_tile(p);

        for (int li = 0; li < NIT; li++) {
            int stg = li % NSTG;
            mbar_wait(FULL0 + 8 * stg, (uint32_t)((li / NSTG) & 1));
            uint32_t base = sb + 1024 + (uint32_t)stg * STG;
            uint64_t bd = DESC_BASE | ((uint64_t)((base + MT * ACH) >> 4) & 0x3FFF);
#pragma unroll
            for (int mt = 0; mt < MT; mt++) {
                uint64_t ad = DESC_BASE | ((uint64_t)((base + mt * ACH) >> 4) & 0x3FFF);
#pragma unroll
                for (int k = 0; k < 4; k++)
                    mma_tf32(tmem + mt * BN, ad + k * 2, bd + k * 2, IDESC,
                             (uint32_t)((li | k) != 0));
            }
            asm volatile(
                "tcgen05.commit.cta_group::1.mbarrier::arrive::one.shared::cluster.b64 [%0];"
                :: "r"(DONE0 + 8 * (li & 3)) : "memory");
            if (li >= LAG) {
                int j = li - LAG;
                mbar_wait(DONE0 + 8 * (j & 3), (uint32_t)((j >> 2) & 1));
                if (j + NSTG < NIT) load_tile(j + NSTG);
            }
        }
        for (int j = (NIT - LAG > 0 ? NIT - LAG : 0); j < NIT; j++)
            mbar_wait(DONE0 + 8 * (j & 3), (uint32_t)((j >> 2) & 1));
    }
    __syncthreads();

    constexpr int RS = BN + 4;
    float* sc = (float*)(smem + 1024);
    asm volatile("tcgen05.fence::after_thread_sync;" ::: "memory");
#pragma unroll
    for (int mt = 0; mt < MT; mt++) {
        if (wid < 4) {
            int rloc = wid * 32 + lane;
#pragma unroll
            for (int cb = 0; cb < BN; cb += 32) {
                uint32_t d[32];
                asm volatile(
                    "tcgen05.ld.sync.aligned.32x32b.x32.b32 "
                    "{%0, %1, %2, %3, %4, %5, %6, %7, "
                    " %8, %9, %10, %11, %12, %13, %14, %15, "
                    " %16, %17, %18, %19, %20, %21, %22, %23, "
                    " %24, %25, %26, %27, %28, %29, %30, %31}, [%32];"
                    : "=r"(d[0]), "=r"(d[1]), "=r"(d[2]), "=r"(d[3]),
                      "=r"(d[4]), "=r"(d[5]), "=r"(d[6]), "=r"(d[7]),
                      "=r"(d[8]), "=r"(d[9]), "=r"(d[10]), "=r"(d[11]),
                      "=r"(d[12]), "=r"(d[13]), "=r"(d[14]), "=r"(d[15]),
                      "=r"(d[16]), "=r"(d[17]), "=r"(d[18]), "=r"(d[19]),
                      "=r"(d[20]), "=r"(d[21]), "=r"(d[22]), "=r"(d[23]),
                      "=r"(d[24]), "=r"(d[25]), "=r"(d[26]), "=r"(d[27]),
                      "=r"(d[28]), "=r"(d[29]), "=r"(d[30]), "=r"(d[31])
                    : "r"(tmem + mt * BN + cb));
                asm volatile("tcgen05.wait::ld.sync.aligned;" ::: "memory");
                float* row = sc + rloc * RS + cb;
#pragma unroll
                for (int c = 0; c < 32; c += 4)
                    *(float4*)(row + c) = make_float4(__uint_as_float(d[c]),
                                                      __uint_as_float(d[c + 1]),
                                                      __uint_as_float(d[c + 2]),
                                                      __uint_as_float(d[c + 3]));
            }
            asm volatile("tcgen05.fence::before_thread_sync;" ::: "memory");
        }
        __syncthreads();
        int rb = bm + mt * 128;
        for (int idx = tid; idx < 128 * (BN / 4); idx += 128) {
            int r = idx / (BN / 4), q = idx % (BN / 4);
            if (rb + r < NN) {
                float4 v = *(float4*)(sc + r * RS + q * 4);
                if (EMB) {
                    float4 bv = *(const float4*)(bias + bn + q * 4);
                    v.x += bv.x; v.y += bv.y; v.z += bv.z; v.w += bv.w;
                    *(float4*)(C + (size_t)(rb + r) * ldc + bn + q * 4) = v;
                } else {
                    atomicAdd((float4*)(C + (size_t)(rb + r) * ldc + bn + q * 4), v);
                }
            }
        }
        __syncthreads();
    }
    if (wid == 0) {
        asm volatile("tcgen05.relinquish_alloc_permit.cta_group::1.sync.aligned;");
        asm volatile("tcgen05.dealloc.cta_group::1.sync.aligned.b32 %0, %1;"
                     :: "r"(tmem), "r"(TCOLS));
    }
#else
    (void)tmA; (void)tmB; (void)bias; (void)C; (void)ldc; (void)zc; (void)CSP; (void)CTOT;
#endif
}

// ---------------- per-edge message MLP + scatter --------------------------
// __launch_bounds__(256, 1): allow high reg count so m1/m2/eav stay in
// registers (eliminates local-memory spill traffic through L1TEX).
template <bool COORD>
__global__ void __launch_bounds__(256, 1) k_edge(const int* __restrict__ ei,
                                                 const float* __restrict__ mw1l,
                                                 const float* __restrict__ mb1l,
                                                 const float* __restrict__ mw2l,
                                                 const float* __restrict__ mb2l,
                                                 const float* __restrict__ cw1l,
                                                 const float* __restrict__ cb1l,
                                                 const float* __restrict__ cw2l) {
    __shared__ float sEA[16 * 24];
    __shared__ float sWr[24], sB1[24], sB2[24];
    __shared__ float sW2[24 * 24];
    __shared__ float sC1[24 * 24], sCB[24], sC2[24];
    int tid = threadIdx.x;
    for (int i = tid; i < 16 * 24; i += 256) sEA[i] = mw1l[2560 * 24 + i];
    for (int i = tid; i < 576; i += 256) sW2[i] = mw2l[i];
    if (tid < 24) {
        sWr[tid] = mw1l[2576 * 24 + tid];
        sB1[tid] = mb1l[tid];
        sB2[tid] = mb2l[tid];
    }
    if (COORD) {
        for (int i = tid; i < 576; i += 256) sC1[i] = cw1l[i];
        if (tid < 24) {
            sCB[tid] = cb1l[tid];
            sC2[tid] = cw2l[tid];
        }
    }
    __syncthreads();
    int e = blockIdx.x * 256 + tid;
    if (e >= EDGES) return;
    int src = ei[e], dst = ei[EDGES + e];
    float px = g_pos[src * 3 + 0] - g_pos[dst * 3 + 0];
    float py = g_pos[src * 3 + 1] - g_pos[dst * 3 + 1];
    float pz = g_pos[src * 3 + 2] - g_pos[dst * 3 + 2];
    float radial = px * px + py * py + pz * pz;

    float eav[16];
    {
        const float4* ea4 = (const float4*)(g_ea + (size_t)e * 16);
#pragma unroll
        for (int q = 0; q < 4; q++) {
            float4 v = ea4[q];
            eav[4 * q + 0] = v.x;
            eav[4 * q + 1] = v.y;
            eav[4 * q + 2] = v.z;
            eav[4 * q + 3] = v.w;
        }
    }

    float m1[24];
    const float4* pa = (const float4*)(g_proj + (size_t)dst * PROJW);
    const float4* pb = (const float4*)(g_proj + (size_t)src * PROJW + 24);
#pragma unroll
    for (int q = 0; q < 6; q++) {
        float4 a = pa[q], b = pb[q];
        m1[4 * q + 0] = a.x + b.x;
        m1[4 * q + 1] = a.y + b.y;
        m1[4 * q + 2] = a.z + b.z;
        m1[4 * q + 3] = a.w + b.w;
    }
#pragma unroll
    for (int k = 0; k < 24; k++) m1[k] += sB1[k] + radial * sWr[k];
#pragma unroll
    for (int f = 0; f < 16; f++) {
        float av = eav[f];
#pragma unroll
        for (int k = 0; k < 24; k++) m1[k] += av * sEA[f * 24 + k];
    }
#pragma unroll
    for (int k = 0; k < 24; k++) m1[k] = silu_f(m1[k]);

    float m2[24];
#pragma unroll
    for (int k = 0; k < 24; k++) m2[k] = sB2[k];
#pragma unroll
    for (int j = 0; j < 24; j++) {
        float mv = m1[j];
#pragma unroll
        for (int k = 0; k < 24; k++) m2[k] += mv * sW2[j * 24 + k];
    }
#pragma unroll
    for (int k = 0; k < 24; k++) m2[k] = silu_f(m2[k]);

    float* agg = g_magg + (size_t)dst * 24;
#if __CUDA_ARCH__ >= 900
#pragma unroll
    for (int q = 0; q < 6; q++)
        atomicAdd((float4*)(agg + q * 4),
                  make_float4(m2[q * 4], m2[q * 4 + 1], m2[q * 4 + 2], m2[q * 4 + 3]));
#else
#pragma unroll
    for (int k = 0; k < 24; k++) atomicAdd(agg + k, m2[k]);
#endif

    if (COORD) {
        float w = 0.f;
#pragma unroll
        for (int k = 0; k < 24; k++) {
            float t = sCB[k];
#pragma unroll
            for (int j = 0; j < 24; j++) t += m2[j] * sC1[j * 24 + k];
            w += silu_f(t) * sC2[k];
        }
        atomicAdd(&g_pd[dst * 3 + 0], px * w);
        atomicAdd(&g_pd[dst * 3 + 1], py * w);
        atomicAdd(&g_pd[dst * 3 + 2], pz * w);
    }
}

// ---------------- per-node: node MLP + residual + LayerNorm + pos ---------
__global__ void __launch_bounds__(320) k_node(const float* __restrict__ nw1l,
                                              const float* __restrict__ nb1l,
                                              const float* __restrict__ nw2l,
                                              const float* __restrict__ nb2l,
                                              const float* __restrict__ lngl,
                                              const float* __restrict__ lnbl) {
    __shared__ float sW1m[576];
    __shared__ float sNB1[24];
    __shared__ float sT[4 * 24];
    __shared__ float sRed[10 * 8];
    __shared__ float sMu[4], sRs[4];

    int tid = threadIdx.x;
    int lane = tid & 31, wid = tid >> 5;
    int d0 = tid * 4;

    float4 w2[24];
#pragma unroll
    for (int m = 0; m < 24; m++) w2[m] = *(const float4*)(nw2l + m * DD + d0);
    float4 b2 = *(const float4*)(nb2l + d0);
    float4 gg = *(const float4*)(lngl + d0);
    float4 bb = *(const float4*)(lnbl + d0);

    for (int i = tid; i < 576; i += 320) sW1m[i] = nw1l[1280 * 24 + i];
    if (tid < 24) sNB1[tid] = nb1l[tid];
    __syncthreads();

    for (int i0 = blockIdx.x * 4; i0 < NN; i0 += gridDim.x * 4) {
        float4 hv[4];
#pragma unroll
        for (int b = 0; b < 4; b++) {
            int node = i0 + b;
            if (node < NN) hv[b] = *(const float4*)(g_h + (size_t)node * DD + d0);
        }

        if (wid < 4) {
            int node = i0 + wid;
            if (node < NN) {
                int lk = (lane < 24) ? lane : 0;
                float inv = 1.f / fmaxf(g_deg[node], 1.f);
                float ms = g_magg[(size_t)node * 24 + lk] * inv;
                float t = sNB1[lk] + g_proj[(size_t)node * PROJW + 48 + lk];
#pragma unroll
                for (int k = 0; k < 24; k++) {
                    float msk = __shfl_sync(0xffffffff, ms, k);
                    t += msk * sW1m[k * 24 + lk];
                }
                __syncwarp();
                if (lane < 24) {
                    sT[wid * 24 + lane] = silu_f(t);
                    g_magg[(size_t)node * 24 + lane] = 0.f;
                    *(float4*)(g_proj + (size_t)node * PROJW + lane * 4) =
                        make_float4(0.f, 0.f, 0.f, 0.f);
                }
            }
        } else if (wid == 4 && lane < 12) {
            int node = i0 + lane / 3, c = lane % 3;
            if (node < NN) {
                g_pos[node * 3 + c] += g_pd[node * 3 + c];
                g_pd[node * 3 + c] = 0.f;
            }
        }
        __syncthreads();

        float4 hn[4];
        float s[4], ss[4];
#pragma unroll
        for (int b = 0; b < 4; b++) {
            int node = i0 + b;
            s[b] = 0.f; ss[b] = 0.f;
            if (node < NN) {
                float4 acc = b2;
#pragma unroll
                for (int m = 0; m < 24; m++) {
                    float t = sT[b * 24 + m];
                    acc.x += t * w2[m].x;
                    acc.y += t * w2[m].y;
                    acc.z += t * w2[m].z;
                    acc.w += t * w2[m].w;
                }
                hn[b].x = hv[b].x + acc.x;
                hn[b].y = hv[b].y + acc.y;
                hn[b].z = hv[b].z + acc.z;
                hn[b].w = hv[b].w + acc.w;
                s[b] = hn[b].x + hn[b].y + hn[b].z + hn[b].w;
                ss[b] = hn[b].x * hn[b].x + hn[b].y * hn[b].y +
                        hn[b].z * hn[b].z + hn[b].w * hn[b].w;
            }
        }
#pragma unroll
        for (int off = 16; off > 0; off >>= 1) {
#pragma unroll
            for (int b = 0; b < 4; b++) {
                s[b] += __shfl_down_sync(0xffffffff, s[b], off);
                ss[b] += __shfl_down_sync(0xffffffff, ss[b], off);
            }
        }
        if (lane == 0) {
#pragma unroll
            for (int b = 0; b < 4; b++) {
                sRed[wid * 8 + b * 2] = s[b];
                sRed[wid * 8 + b * 2 + 1] = ss[b];
            }
        }
        __syncthreads();
        if (tid < 4) {
            float S = 0.f, SS = 0.f;
#pragma unroll
            for (int w = 0; w < 10; w++) {
                S += sRed[w * 8 + tid * 2];
                SS += sRed[w * 8 + tid * 2 + 1];
            }
            float mu = S * (1.f / 1280.f);
            float var = SS * (1.f / 1280.f) - mu * mu;
            sMu[tid] = mu;
            sRs[tid] = rsqrtf(var + 1e-5f);
        }
        __syncthreads();
#pragma unroll
        for (int b = 0; b < 4; b++) {
            int node = i0 + b;
            if (node < NN) {
                float mu = sMu[b], rs = sRs[b];
                float4 o;
                o.x = (hn[b].x - mu) * rs * gg.x + bb.x;
                o.y = (hn[b].y - mu) * rs * gg.y + bb.y;
                o.z = (hn[b].z - mu) * rs * gg.z + bb.z;
                o.w = (hn[b].w - mu) * rs * gg.w + bb.w;
                *(float4*)(g_h + (size_t)node * DD + d0) = o;
            }
        }
        __syncthreads();
    }
}

typedef CUresult (*tmap_fn_t)(CUtensorMap*, CUtensorMapDataType, cuuint32_t, void*,
                              const cuuint64_t*, const cuuint64_t*, const cuuint32_t*,
                              const cuuint32_t*, CUtensorMapInterleave, CUtensorMapSwizzle,
                              CUtensorMapL2promotion, CUtensorMapFloatOOBfill);

static tmap_fn_t get_tmap_fn() {
    static tmap_fn_t fn = nullptr;
    if (!fn) {
        void* p = nullptr;
        cudaDriverEntryPointQueryResult st;
        cudaGetDriverEntryPoint("cuTensorMapEncodeTiled", &p, cudaEnableDefault, &st);
        fn = (tmap_fn_t)p;
    }
    return fn;
}

static void make_tmap(CUtensorMap* tm, void* base, uint64_t d0, uint64_t d1, uint64_t d2,
                      uint64_t s1, uint64_t s2, uint32_t b0, uint32_t b1) {
    cuuint64_t dims[3] = {d0, d1, d2};
    cuuint64_t strides[2] = {s1, s2};
    cuuint32_t box[3] = {b0, b1, 1};
    cuuint32_t es[3] = {1, 1, 1};
    get_tmap_fn()(tm, CU_TENSOR_MAP_DATA_TYPE_FLOAT32, 3, base, dims, strides, box, es,
                  CU_TENSOR_MAP_INTERLEAVE_NONE, CU_TENSOR_MAP_SWIZZLE_128B,
                  CU_TENSOR_MAP_L2_PROMOTION_L2_128B, CU_TENSOR_MAP_FLOAT_OOB_FILL_NONE);
}

extern "C" void kernel_launch(void* const* d_in, const int* in_sizes, int n_in,
                              void* d_out, int out_size) {
    const float* h0 = (const float*)d_in[0];
    const float* pos0 = (const float*)d_in[1];
    const int* ei = (const int*)d_in[2];
    const float* embW = (const float*)d_in[3];
    const float* embB = (const float*)d_in[4];
    const float* mw1 = (const float*)d_in[5];
    const float* mb1 = (const float*)d_in[6];
    const float* mw2 = (const float*)d_in[7];
    const float* mb2 = (const float*)d_in[8];
    const float* cw1 = (const float*)d_in[9];
    const float* cb1 = (const float*)d_in[10];
    const float* cw2 = (const float*)d_in[11];
    const float* nw1 = (const float*)d_in[12];
    const float* nb1 = (const float*)d_in[13];
    const float* nw2 = (const float*)d_in[14];
    const float* nb2 = (const float*)d_in[15];
    const float* lng = (const float*)d_in[16];
    const float* lnb = (const float*)d_in[17];
    float* out = (float*)d_out;

    const int SMEM_EMB = 1024 + 3 * (2 * 128 * 128 + 256 * 128);
    const int SMEM_PROJ = 1024 + 4 * (2 * 128 * 128 + PROJW * 128);

    cudaFuncSetAttribute(k_mma<256, 2, true, 3, 1>,
                         cudaFuncAttributeMaxDynamicSharedMemorySize, SMEM_EMB);
    cudaFuncSetAttribute(k_mma<PROJW, 2, false, 4, 2>,
                         cudaFuncAttributeMaxDynamicSharedMemorySize, SMEM_PROJ);

    void* p_pos = nullptr;
    void* p_h = nullptr;
    void* p_proj = nullptr;
    void* p_wT = nullptr;
    void* p_wpack = nullptr;
    void* p_deg = nullptr;
    void* p_magg = nullptr;
    void* p_pd = nullptr;
    cudaGetSymbolAddress(&p_pos, g_pos);
    cudaGetSymbolAddress(&p_h, g_h);
    cudaGetSymbolAddress(&p_proj, g_proj);
    cudaGetSymbolAddress(&p_wT, g_wT);
    cudaGetSymbolAddress(&p_wpack, g_wpack);
    cudaGetSymbolAddress(&p_deg, g_deg);
    cudaGetSymbolAddress(&p_magg, g_magg);
    cudaGetSymbolAddress(&p_pd, g_pd);

    CUtensorMap tmA_emb, tmB_emb, tmA_proj, tmB_proj;
    make_tmap(&tmA_emb, (void*)h0, DD, NN, 1, (uint64_t)DD * 4, (uint64_t)DD * NN * 4, 32, 128);
    make_tmap(&tmB_emb, p_wT, DD, DD, 1, (uint64_t)DD * 4, (uint64_t)DD * DD * 4, 32, 256);
    make_tmap(&tmA_proj, p_h, DD, NN, 1, (uint64_t)DD * 4, (uint64_t)DD * NN * 4, 32, 128);
    make_tmap(&tmB_proj, p_wpack, DD, PROJW, LL, (uint64_t)DD * 4,
              (uint64_t)DD * PROJW * 4, 32, PROJW);

    // zero accumulators via async memsets (graph-capturable, race-free)
    cudaMemsetAsync(p_deg, 0, NN * sizeof(float), 0);
    cudaMemsetAsync(p_magg, 0, (size_t)NN * MM * sizeof(float), 0);
    cudaMemsetAsync(p_pd, 0, NN * 3 * sizeof(float), 0);
    cudaMemsetAsync(p_proj, 0, (size_t)NN * PROJW * sizeof(float), 0);
    cudaMemcpyAsync(p_pos, pos0, NN * 3 * sizeof(float), cudaMemcpyDeviceToDevice, 0);

    k_prep<<<(DD * DD + 255) / 256, 256>>>(embW, mw1, nw1, ei, pos0);

    k_mma<256, 2, true, 3, 1><<<dim3(5, 40), 128, SMEM_EMB>>>(
        tmA_emb, tmB_emb, embB, (float*)p_h, DD, 0, 0, DD / 32);

    for (int l = 0; l < LL; l++) {
        k_mma<PROJW, 2, false, 4, 2><<<dim3(3, 40), 128, SMEM_PROJ>>>(
            tmA_proj, tmB_proj, nullptr, (float*)p_proj, PROJW, l, 14, DD / 32);

        const float* mw1l = mw1 + (size_t)l * 2577 * 24;
        if (l < LL - 1) {
            k_edge<true><<<(EDGES + 255) / 256, 256>>>(
                ei, mw1l, mb1 + l * 24, mw2 + l * 576, mb2 + l * 24,
                cw1 + l * 576, cb1 + l * 24, cw2 + l * 24);
        } else {
            k_edge<false><<<(EDGES + 255) / 256, 256>>>(
                ei, mw1l, mb1 + l * 24, mw2 + l * 576, mb2 + l * 24,
                nullptr, nullptr, nullptr);
        }
        k_node<<<148, 320>>>(
            nw1 + (size_t)l * 1304 * 24, nb1 + l * 24,
            nw2 + (size_t)l * 24 * 1280, nb2 + l * 1280,
            lng + l * 1280, lnb + l * 1280);
    }

    cudaMemcpyAsync(out, p_h, (size_t)NN * DD * sizeof(float), cudaMemcpyDeviceToDevice, 0);
    cudaMemcpyAsync(out + (size_t)NN * DD, p_pos, NN * 3 * sizeof(float), cudaMemcpyDeviceToDevice, 0);
}